// round 10
// baseline (speedup 1.0000x reference)
#include <cuda_runtime.h>
#include <cstdint>
#include <math.h>

// ============================================================
// CustomMLP: out = gelu(X @ W1 + b1) @ W2 + b2
//   X [8192,1024] fp32   W1 [1024,4096]   W2 [4096,1024]
// mma.sync.m16n8k8 tf32 path (harness ptxas = plain sm_103).
// R7 measured: 987us, tensor=47%, occ=12.1%, regs=242 ->
// latency-bound. R10 carries the occupancy fix: warp tile 64x32,
// 256 thr (8 warps 2Mx4N), launch_bounds(256,2) caps regs at 128
// -> 16 warps/SM; single barrier per k-block (3-stage ring makes
// the trailing one redundant); kb loop pinned to no-unroll to
// keep the mainloop inside L0 I$.
// BM=BN=128, BK=32, cp.async 3-stage, k-PERMUTED operands
// (p = (k&3)*8 + k>>2 per 32-block) -> LDS.128 fragment loads.
// GEMM1 epilogue restaged through smem for STG.128 stores.
// ============================================================

#define DINLINE __device__ __forceinline__

// ---------------- scratch (no cudaMalloc allowed) ----------------
__device__ alignas(1024) float g_xr [8192ull * 1024];   // X, tf32, k-permuted
__device__ alignas(1024) float g_w1t[4096ull * 1024];   // W1^T [N,K], tf32, k-perm
__device__ alignas(1024) float g_w2t[1024ull * 4096];   // W2^T [N,K], tf32, k-perm
__device__ alignas(1024) float g_h  [8192ull * 4096];   // gelu(.), tf32, k-perm

// ---------------- tile geometry ----------------
constexpr int BM = 128;
constexpr int BN = 128;
constexpr int BK = 32;             // one permuted k-block
constexpr int THREADS = 256;       // 8 warps: 2 (M) x 4 (N), 64x32 warp tile
constexpr int NSTAGES = 3;

constexpr int PAD = 4;             // floats of padding per row
constexpr int LDT = BK + PAD;      // 36 floats row stride
constexpr int LDT4 = LDT / 4;      // 9 float4 per row
constexpr int TILE_B = BM * LDT * 4;          // 18432 bytes per tile
constexpr int STG_B  = 2 * TILE_B;            // 36864 bytes per stage (A+B)
constexpr int SMEM_TOTAL = NSTAGES * STG_B;   // 110592 bytes

// epilogue restage: 128 rows x 132-float stride = 67584 B <= SMEM_TOTAL
constexpr int ERS = 132;

// ---------------- helpers ----------------
DINLINE void cp16(void* s, const void* g) {
    uint32_t a;
    asm("{ .reg .u64 t; cvta.to.shared.u64 t, %1; cvt.u32.u64 %0, t; }"
        : "=r"(a) : "l"(s));
    asm volatile("cp.async.cg.shared.global [%0], [%1], 16;" :: "r"(a), "l"(g));
}
DINLINE void cp_commit() { asm volatile("cp.async.commit_group;" ::: "memory"); }
DINLINE void cp_wait0()  { asm volatile("cp.async.wait_group 0;" ::: "memory"); }
DINLINE void cp_wait1()  { asm volatile("cp.async.wait_group 1;" ::: "memory"); }

DINLINE void mma_tf32(float* d, uint32_t a0, uint32_t a1, uint32_t a2, uint32_t a3,
                      uint32_t b0, uint32_t b1) {
    asm volatile(
        "mma.sync.aligned.m16n8k8.row.col.f32.tf32.tf32.f32 "
        "{%0,%1,%2,%3}, {%4,%5,%6,%7}, {%8,%9}, {%0,%1,%2,%3};"
        : "+f"(d[0]), "+f"(d[1]), "+f"(d[2]), "+f"(d[3])
        : "r"(a0), "r"(a1), "r"(a2), "r"(a3), "r"(b0), "r"(b1));
}

DINLINE float rnd_tf32(float v) {
    uint32_t u;
    asm("cvt.rna.tf32.f32 %0, %1;" : "=r"(u) : "f"(v));
    return __uint_as_float(u);
}
DINLINE uint32_t f2u(float v) { return __float_as_uint(v); }

// ---------------- prep kernels ----------------
// round to tf32 and write k-permuted. K = row length (multiple of 32).
__global__ void cvt_tf32_perm_kernel(const float4* __restrict__ in,
                                     float* __restrict__ out, int K, int n4) {
    int i = blockIdx.x * blockDim.x + threadIdx.x;
    if (i >= n4) return;
    float4 v = in[i];
    int e = i * 4;                  // element index; all 4 in same 32-block
    int m = e / K;
    int k = e - m * K;
    int j = (k >> 2) & 7;
    float* rp = out + (size_t)m * K + (k & ~31);
    rp[j]      = rnd_tf32(v.x);     // (k&3)==0 -> position 0*8+j
    rp[8 + j]  = rnd_tf32(v.y);
    rp[16 + j] = rnd_tf32(v.z);
    rp[24 + j] = rnd_tf32(v.w);
}

// out[C,R] = tf32(in[R,C]^T), out columns (R = K dim) k-permuted. block (32,8)
__global__ void transpose_cvt_perm_kernel(const float* __restrict__ in,
                                          float* __restrict__ out, int R, int C) {
    __shared__ float tile[32][33];
    int c0 = blockIdx.x * 32, r0 = blockIdx.y * 32;
    #pragma unroll
    for (int i = 0; i < 32; i += 8)
        tile[threadIdx.y + i][threadIdx.x] =
            in[(size_t)(r0 + threadIdx.y + i) * C + c0 + threadIdx.x];
    __syncthreads();
    int kp = r0 + (((int)threadIdx.x & 3) << 3) + ((int)threadIdx.x >> 2);
    #pragma unroll
    for (int i = 0; i < 32; i += 8)
        out[(size_t)(c0 + threadIdx.y + i) * R + kp] =
            rnd_tf32(tile[threadIdx.x][threadIdx.y + i]);
}

// ---------------- tile loads (gmem -> smem, cp.async) ----------------
// 256 threads: tid&7 = 16B chunk, tid>>3 = base row (0..31); 4 rows each A, B.
template<int KG>
DINLINE void load_tiles(const float* __restrict__ A, const float* __restrict__ Bt,
                        int m0, int n0, int kb, char* stage) {
    const int tid = threadIdx.x;
    const int c = tid & 7;
    const int r0 = tid >> 3;
    const int kcol = kb * BK + c * 4;
    float* sA = reinterpret_cast<float*>(stage);
    float* sB = reinterpret_cast<float*>(stage + TILE_B);
    #pragma unroll
    for (int t = 0; t < 4; t++) {
        int row = r0 + t * 32;
        cp16(sA + row * LDT + c * 4, A  + (size_t)(m0 + row) * KG + kcol);
        cp16(sB + row * LDT + c * 4, Bt + (size_t)(n0 + row) * KG + kcol);
    }
}

template<bool G>
DINLINE float epi_op(float acc, float b) {
    float t = acc + b;
    if (G) {
        t = 0.5f * t * (1.0f + erff(t * 0.70710678118654752f));
        t = rnd_tf32(t);   // h feeds the tf32 GEMM2
    }
    return t;
}

// ---------------- GEMM: C[BMxBN] = A[m0:,:] @ Bt[n0:,:]^T (+bias, opt gelu) ----------------
template<int KG, int NG, bool DO_GELU>
__global__ void __launch_bounds__(THREADS, 2)
mlp_gemm_kernel(const float* __restrict__ A, const float* __restrict__ Bt,
                const float* __restrict__ bias, float* __restrict__ C) {
    extern __shared__ char smem[];
    const int tid  = threadIdx.x;
    const int lane = tid & 31;
    const int warp = tid >> 5;
    const int wm = warp & 1;          // 2 warps along M (64 rows each)
    const int wn = warp >> 1;         // 4 warps along N (32 cols each)
    const int g  = lane >> 2;         // groupID (0..7)
    const int tk = lane & 3;          // threadID_in_group (0..3)
    const int m0 = blockIdx.y * BM, n0 = blockIdx.x * BN;
    const int KT = KG / BK;

    float acc[4][4][4];               // [mt][nt][frag] -> 64 regs
    #pragma unroll
    for (int i = 0; i < 4; i++)
        #pragma unroll
        for (int j = 0; j < 4; j++)
            #pragma unroll
            for (int q = 0; q < 4; q++) acc[i][j][q] = 0.0f;

    // prologue: prefetch stages 0, 1
    load_tiles<KG>(A, Bt, m0, n0, 0, smem);
    cp_commit();
    load_tiles<KG>(A, Bt, m0, n0, 1, smem + STG_B);
    cp_commit();

    // no-unroll: body has full ILP already; unrolling KT (32/128 iters)
    // would blow past L0 I$ (~6KB) and add fetch overhead per instr.
    #pragma unroll 1
    for (int kb = 0; kb < KT; kb++) {
        if (kb + 1 < KT) cp_wait1(); else cp_wait0();   // stage kb resident
        __syncthreads();
        // Single barrier per iteration is sufficient with 3 stages:
        // iteration kb's new loads write buffer (kb+2)%3, whose last readers
        // (iteration kb-1) are already past this barrier; kb%3 != (kb+2)%3.
        if (kb + 2 < KT) {
            load_tiles<KG>(A, Bt, m0, n0, kb + 2, smem + ((kb + 2) % NSTAGES) * STG_B);
            cp_commit();
        }
        const char* stage = smem + (kb % NSTAGES) * STG_B;
        const float4* sA4 = reinterpret_cast<const float4*>(stage);
        const float4* sB4 = reinterpret_cast<const float4*>(stage + TILE_B);

        // permuted layout: float4 at r*9 + 2*tk + p holds, for phase p,
        // k-steps ks=2p,2p+1: (.x,.y)=(a0,a2)|(b0,b1)@ks=2p; (.z,.w)@ks=2p+1.
        #pragma unroll
        for (int p = 0; p < 2; p++) {
            float4 bqv[4];
            #pragma unroll
            for (int nt = 0; nt < 4; nt++) {
                int n = wn * 32 + nt * 8 + g;
                bqv[nt] = sB4[n * LDT4 + 2 * tk + p];
            }
            #pragma unroll
            for (int mt = 0; mt < 4; mt++) {
                int r = wm * 64 + mt * 16 + g;
                float4 aLo = sA4[r * LDT4 + 2 * tk + p];
                float4 aHi = sA4[(r + 8) * LDT4 + 2 * tk + p];
                #pragma unroll
                for (int s = 0; s < 2; s++) {
                    uint32_t a0 = f2u(s ? aLo.z : aLo.x);
                    uint32_t a1 = f2u(s ? aHi.z : aHi.x);
                    uint32_t a2 = f2u(s ? aLo.w : aLo.y);
                    uint32_t a3 = f2u(s ? aHi.w : aHi.y);
                    #pragma unroll
                    for (int nt = 0; nt < 4; nt++) {
                        uint32_t b0 = f2u(s ? bqv[nt].z : bqv[nt].x);
                        uint32_t b1 = f2u(s ? bqv[nt].w : bqv[nt].y);
                        mma_tf32(acc[mt][nt], a0, a1, a2, a3, b0, b1);
                    }
                }
            }
        }
    }

    // ---------------- epilogue ----------------
    if (DO_GELU) {
        // GEMM1: gelu + bias, restage the k-PERMUTED tile through smem so
        // global stores are dense STG.128 (100% sector efficiency).
        __syncthreads();   // all MMA smem reads done before overwriting stages
        float* es = reinterpret_cast<float*>(smem);
        #pragma unroll
        for (int mt = 0; mt < 4; mt++) {
            const int lr = wm * 64 + mt * 16 + g;
            #pragma unroll
            for (int nt = 0; nt < 4; nt++) {
                const int lc = wn * 32 + nt * 8 + 2 * tk;
                const int blk = lc & ~31;
                const int k0 = lc & 31;
                const int p0 = ((k0 & 3) << 3) | (k0 >> 2);
                const int p1 = (((k0 + 1) & 3) << 3) | ((k0 + 1) >> 2);
                const float2 bv = *reinterpret_cast<const float2*>(bias + n0 + lc);
                es[lr * ERS + blk + p0]       = epi_op<true>(acc[mt][nt][0], bv.x);
                es[lr * ERS + blk + p1]       = epi_op<true>(acc[mt][nt][1], bv.y);
                es[(lr + 8) * ERS + blk + p0] = epi_op<true>(acc[mt][nt][2], bv.x);
                es[(lr + 8) * ERS + blk + p1] = epi_op<true>(acc[mt][nt][3], bv.y);
            }
        }
        __syncthreads();
        #pragma unroll
        for (int t = 0; t < 16; t++) {
            int idx = t * 256 + tid;          // 0..4095
            int row = idx >> 5;               // 0..127
            int c4  = idx & 31;               // float4 column
            float4 v = *reinterpret_cast<const float4*>(es + row * ERS + c4 * 4);
            *reinterpret_cast<float4*>(C + (size_t)(m0 + row) * NG + n0 + c4 * 4) = v;
        }
    } else {
        // GEMM2: bias only, direct float2 stores (already sector-efficient).
        #pragma unroll
        for (int mt = 0; mt < 4; mt++) {
            const int r = m0 + wm * 64 + mt * 16 + g;
            #pragma unroll
            for (int nt = 0; nt < 4; nt++) {
                const int cN = n0 + wn * 32 + nt * 8 + 2 * tk;
                const float2 bv = *reinterpret_cast<const float2*>(bias + cN);
                float2 v0, v1;
                v0.x = epi_op<false>(acc[mt][nt][0], bv.x);
                v0.y = epi_op<false>(acc[mt][nt][1], bv.y);
                v1.x = epi_op<false>(acc[mt][nt][2], bv.x);
                v1.y = epi_op<false>(acc[mt][nt][3], bv.y);
                *reinterpret_cast<float2*>(C + (size_t)(r)     * NG + cN) = v0;
                *reinterpret_cast<float2*>(C + (size_t)(r + 8) * NG + cN) = v1;
            }
        }
    }
}

// ---------------- launch ----------------
extern "C" void kernel_launch(void* const* d_in, const int* in_sizes, int n_in,
                              void* d_out, int out_size) {
    const float* x  = (const float*)d_in[0];   // [4,2048,1024] -> [8192,1024]
    const float* w1 = (const float*)d_in[1];   // [1024,4096]
    const float* b1 = (const float*)d_in[2];   // [4096]
    const float* w2 = (const float*)d_in[3];   // [4096,1024]
    const float* b2 = (const float*)d_in[4];   // [1024]
    float* out = (float*)d_out;                // [8192,1024]

    float *xr, *w1t, *w2t, *h;
    cudaGetSymbolAddress((void**)&xr,  g_xr);
    cudaGetSymbolAddress((void**)&w1t, g_w1t);
    cudaGetSymbolAddress((void**)&w2t, g_w2t);
    cudaGetSymbolAddress((void**)&h,   g_h);

    cudaFuncSetAttribute(mlp_gemm_kernel<1024, 4096, true>,
                         cudaFuncAttributeMaxDynamicSharedMemorySize, SMEM_TOTAL);
    cudaFuncSetAttribute(mlp_gemm_kernel<4096, 1024, false>,
                         cudaFuncAttributeMaxDynamicSharedMemorySize, SMEM_TOTAL);

    // prep: round to tf32 + k-permute X; transpose+round+permute weights to [N,K]
    {
        int n4 = 8192 * 1024 / 4;
        cvt_tf32_perm_kernel<<<(n4 + 255) / 256, 256>>>((const float4*)x, xr, 1024, n4);
        transpose_cvt_perm_kernel<<<dim3(4096 / 32, 1024 / 32), dim3(32, 8)>>>(w1, w1t, 1024, 4096);
        transpose_cvt_perm_kernel<<<dim3(1024 / 32, 4096 / 32), dim3(32, 8)>>>(w2, w2t, 4096, 1024);
    }

    // GEMM1: h = tf32(gelu(X @ W1 + b1))   [8192 x 4096], h stored k-permuted
    mlp_gemm_kernel<1024, 4096, true>
        <<<dim3(4096 / BN, 8192 / BM), THREADS, SMEM_TOTAL>>>(xr, w1t, b1, h);

    // GEMM2: out = h @ W2 + b2             [8192 x 1024]
    mlp_gemm_kernel<4096, 1024, false>
        <<<dim3(1024 / BN, 8192 / BM), THREADS, SMEM_TOTAL>>>(h, w2t, b2, out);
}

// round 14
// speedup vs baseline: 1.1049x; 1.1049x over previous
#include <cuda_runtime.h>
#include <cstdint>
#include <math.h>

// ============================================================
// CustomMLP: out = gelu(X @ W1 + b1) @ W2 + b2
//   X [8192,1024] fp32   W1 [1024,4096]   W2 [4096,1024]
// mma.sync.m16n8k8 tf32 path (harness ptxas = plain sm_103).
// R7: 987us tensor=47% occ=12% regs=242. R10: 1043us tensor=46%
// occ=24% alu=31% fma=15% -> ALU/IMAD address-arithmetic flood is
// the cap (tensor pipe idle half the time = front-end starvation,
// not dispatch limit). R14 (= R11-R13, carried until measured):
// all mainloop addressing strength-reduced to precomputed uint32
// bases + constant immediates + incremental pointer advance.
// Shape as R10: 256 thr, 64x32 warp tiles, launch_bounds(256,2),
// 3-stage cp.async, single barrier/k-block, k-PERMUTED operands
// -> LDS.128 fragment loads, GEMM1 epilogue restaged for STG.128.
// ============================================================

#define DINLINE __device__ __forceinline__

// ---------------- scratch (no cudaMalloc allowed) ----------------
__device__ alignas(1024) float g_xr [8192ull * 1024];   // X, tf32, k-permuted
__device__ alignas(1024) float g_w1t[4096ull * 1024];   // W1^T [N,K], tf32, k-perm
__device__ alignas(1024) float g_w2t[1024ull * 4096];   // W2^T [N,K], tf32, k-perm
__device__ alignas(1024) float g_h  [8192ull * 4096];   // gelu(.), tf32, k-perm

// ---------------- tile geometry ----------------
constexpr int BM = 128;
constexpr int BN = 128;
constexpr int BK = 32;             // one permuted k-block
constexpr int THREADS = 256;       // 8 warps: 2 (M) x 4 (N), 64x32 warp tile
constexpr int NSTAGES = 3;

constexpr int PAD = 4;             // floats of padding per row
constexpr int LDT = BK + PAD;      // 36 floats row stride (144 bytes)
constexpr int ROWB = LDT * 4;      // 144 bytes per row
constexpr int TILE_B = BM * ROWB;  // 18432 bytes per tile
constexpr int STG_B  = 2 * TILE_B; // 36864 bytes per stage (A+B)
constexpr int SMEM_TOTAL = NSTAGES * STG_B;   // 110592 bytes

// byte-offset constants for the mainloop (all compile-time)
constexpr int ROW32 = 32 * ROWB;   // 4608: 32 rows (cp.async t-step)
constexpr int MT16  = 16 * ROWB;   // 2304: mt step (16 rows)
constexpr int NT8   = 8 * ROWB;    // 1152: nt step / aHi offset (8 rows)

// epilogue restage: 128 rows x 132-float stride = 67584 B <= SMEM_TOTAL
constexpr int ERS = 132;

// ---------------- helpers ----------------
DINLINE uint32_t smem_u32(const void* p) {
    uint32_t a;
    asm("{ .reg .u64 t; cvta.to.shared.u64 t, %1; cvt.u32.u64 %0, t; }"
        : "=r"(a) : "l"(p));
    return a;
}
DINLINE void cp16a(uint32_t s, const float* g) {
    asm volatile("cp.async.cg.shared.global [%0], [%1], 16;" :: "r"(s), "l"(g));
}
DINLINE void cp_commit() { asm volatile("cp.async.commit_group;" ::: "memory"); }
DINLINE void cp_wait0()  { asm volatile("cp.async.wait_group 0;" ::: "memory"); }
DINLINE void cp_wait1()  { asm volatile("cp.async.wait_group 1;" ::: "memory"); }

DINLINE float4 lds128(uint32_t addr) {
    float4 v;
    asm volatile("ld.shared.v4.f32 {%0,%1,%2,%3}, [%4];"
                 : "=f"(v.x), "=f"(v.y), "=f"(v.z), "=f"(v.w) : "r"(addr));
    return v;
}

DINLINE void mma_tf32(float* d, uint32_t a0, uint32_t a1, uint32_t a2, uint32_t a3,
                      uint32_t b0, uint32_t b1) {
    asm volatile(
        "mma.sync.aligned.m16n8k8.row.col.f32.tf32.tf32.f32 "
        "{%0,%1,%2,%3}, {%4,%5,%6,%7}, {%8,%9}, {%0,%1,%2,%3};"
        : "+f"(d[0]), "+f"(d[1]), "+f"(d[2]), "+f"(d[3])
        : "r"(a0), "r"(a1), "r"(a2), "r"(a3), "r"(b0), "r"(b1));
}

DINLINE float rnd_tf32(float v) {
    uint32_t u;
    asm("cvt.rna.tf32.f32 %0, %1;" : "=r"(u) : "f"(v));
    return __uint_as_float(u);
}
DINLINE uint32_t f2u(float v) { return __float_as_uint(v); }

// ---------------- prep kernels ----------------
// round to tf32 and write k-permuted. K = row length (multiple of 32).
__global__ void cvt_tf32_perm_kernel(const float4* __restrict__ in,
                                     float* __restrict__ out, int K, int n4) {
    int i = blockIdx.x * blockDim.x + threadIdx.x;
    if (i >= n4) return;
    float4 v = in[i];
    int e = i * 4;                  // element index; all 4 in same 32-block
    int m = e / K;
    int k = e - m * K;
    int j = (k >> 2) & 7;
    float* rp = out + (size_t)m * K + (k & ~31);
    rp[j]      = rnd_tf32(v.x);     // (k&3)==0 -> position 0*8+j
    rp[8 + j]  = rnd_tf32(v.y);
    rp[16 + j] = rnd_tf32(v.z);
    rp[24 + j] = rnd_tf32(v.w);
}

// out[C,R] = tf32(in[R,C]^T), out columns (R = K dim) k-permuted. block (32,8)
__global__ void transpose_cvt_perm_kernel(const float* __restrict__ in,
                                          float* __restrict__ out, int R, int C) {
    __shared__ float tile[32][33];
    int c0 = blockIdx.x * 32, r0 = blockIdx.y * 32;
    #pragma unroll
    for (int i = 0; i < 32; i += 8)
        tile[threadIdx.y + i][threadIdx.x] =
            in[(size_t)(r0 + threadIdx.y + i) * C + c0 + threadIdx.x];
    __syncthreads();
    int kp = r0 + (((int)threadIdx.x & 3) << 3) + ((int)threadIdx.x >> 2);
    #pragma unroll
    for (int i = 0; i < 32; i += 8)
        out[(size_t)(c0 + threadIdx.y + i) * R + kp] =
            rnd_tf32(tile[threadIdx.x][threadIdx.y + i]);
}

template<bool G>
DINLINE float epi_op(float acc, float b) {
    float t = acc + b;
    if (G) {
        t = 0.5f * t * (1.0f + erff(t * 0.70710678118654752f));
        t = rnd_tf32(t);   // h feeds the tf32 GEMM2
    }
    return t;
}

// ---------------- GEMM: C[BMxBN] = A[m0:,:] @ Bt[n0:,:]^T (+bias, opt gelu) ----------------
template<int KG, int NG, bool DO_GELU>
__global__ void __launch_bounds__(THREADS, 2)
mlp_gemm_kernel(const float* __restrict__ A, const float* __restrict__ Bt,
                const float* __restrict__ bias, float* __restrict__ C) {
    extern __shared__ char smem[];
    const uint32_t sbase = smem_u32(smem);
    const int tid  = threadIdx.x;
    const int lane = tid & 31;
    const int warp = tid >> 5;
    const int wm = warp & 1;          // 2 warps along M (64 rows each)
    const int wn = warp >> 1;         // 4 warps along N (32 cols each)
    const int g  = lane >> 2;         // groupID (0..7)
    const int tk = lane & 3;          // threadID_in_group (0..3)
    const int m0 = blockIdx.y * BM, n0 = blockIdx.x * BN;
    const int KT = KG / BK;

    // ---- hoisted write-side addressing (cp.async targets + gmem sources)
    const int cch = tid & 7;          // 16B chunk
    const int r0w = tid >> 3;         // base row 0..31
    const uint32_t wA = sbase + (uint32_t)(r0w * ROWB + cch * 16);
    const uint32_t wB = wA + TILE_B;
    const float* gA = A  + (size_t)(m0 + r0w) * KG + cch * 4;
    const float* gB = Bt + (size_t)(n0 + r0w) * KG + cch * 4;

    // ---- hoisted read-side bases (stage 0); all loop loads are base+CONST
    const uint32_t rAb = sbase + (uint32_t)((wm * 64 + g) * ROWB + 2 * tk * 16);
    const uint32_t rBb = sbase + TILE_B + (uint32_t)((wn * 32 + g) * ROWB + 2 * tk * 16);

    float acc[4][4][4];               // [mt][nt][frag] -> 64 regs
    #pragma unroll
    for (int i = 0; i < 4; i++)
        #pragma unroll
        for (int j = 0; j < 4; j++)
            #pragma unroll
            for (int q = 0; q < 4; q++) acc[i][j][q] = 0.0f;

    // prologue: prefetch stages 0, 1
    #pragma unroll
    for (int t = 0; t < 4; t++) {
        cp16a(wA + t * ROW32, gA + (size_t)(t * 32) * KG);
        cp16a(wB + t * ROW32, gB + (size_t)(t * 32) * KG);
    }
    cp_commit();
    #pragma unroll
    for (int t = 0; t < 4; t++) {
        cp16a(wA + STG_B + t * ROW32, gA + (size_t)(t * 32) * KG + BK);
        cp16a(wB + STG_B + t * ROW32, gB + (size_t)(t * 32) * KG + BK);
    }
    cp_commit();

    uint32_t stR = 0;                 // read-stage byte offset
    uint32_t stW = 2 * STG_B;         // write-stage byte offset (kb+2)
    const float* gAp = gA + 2 * BK;   // gmem column for kb+2
    const float* gBp = gB + 2 * BK;

    // no-unroll: body has full ILP; keeps mainloop inside L0 I$.
    #pragma unroll 1
    for (int kb = 0; kb < KT; kb++) {
        if (kb + 1 < KT) cp_wait1(); else cp_wait0();   // stage kb resident
        __syncthreads();
        // single barrier per iteration: new loads write buffer (kb+2)%3,
        // whose last readers (iteration kb-1) are already past this barrier.
        if (kb + 2 < KT) {
            const uint32_t a = wA + stW, b = wB + stW;
            #pragma unroll
            for (int t = 0; t < 4; t++) {
                cp16a(a + t * ROW32, gAp + (size_t)(t * 32) * KG);
                cp16a(b + t * ROW32, gBp + (size_t)(t * 32) * KG);
            }
            cp_commit();
        }
        gAp += BK; gBp += BK;
        const uint32_t rA = rAb + stR;
        const uint32_t rB = rBb + stR;

        // permuted layout: float4 at byte base+p*16 holds k-steps 2p,2p+1:
        // (.x,.y)=(a0,a2)|(b0,b1)@ks=2p; (.z,.w)@ks=2p+1.
        #pragma unroll
        for (int p = 0; p < 2; p++) {
            float4 bqv[4];
            #pragma unroll
            for (int nt = 0; nt < 4; nt++)
                bqv[nt] = lds128(rB + nt * NT8 + p * 16);
            #pragma unroll
            for (int mt = 0; mt < 4; mt++) {
                float4 aLo = lds128(rA + mt * MT16 + p * 16);
                float4 aHi = lds128(rA + mt * MT16 + NT8 + p * 16);
                #pragma unroll
                for (int s = 0; s < 2; s++) {
                    uint32_t a0 = f2u(s ? aLo.z : aLo.x);
                    uint32_t a1 = f2u(s ? aHi.z : aHi.x);
                    uint32_t a2 = f2u(s ? aLo.w : aLo.y);
                    uint32_t a3 = f2u(s ? aHi.w : aHi.y);
                    #pragma unroll
                    for (int nt = 0; nt < 4; nt++) {
                        uint32_t b0 = f2u(s ? bqv[nt].z : bqv[nt].x);
                        uint32_t b1 = f2u(s ? bqv[nt].w : bqv[nt].y);
                        mma_tf32(acc[mt][nt], a0, a1, a2, a3, b0, b1);
                    }
                }
            }
        }
        stR = (stR == 2 * STG_B) ? 0u : stR + STG_B;
        stW = (stW == 2 * STG_B) ? 0u : stW + STG_B;
    }

    // ---------------- epilogue ----------------
    if (DO_GELU) {
        // GEMM1: gelu + bias, restage the k-PERMUTED tile through smem so
        // global stores are dense STG.128 (100% sector efficiency).
        __syncthreads();   // all MMA smem reads done before overwriting stages
        float* es = reinterpret_cast<float*>(smem);
        #pragma unroll
        for (int mt = 0; mt < 4; mt++) {
            const int lr = wm * 64 + mt * 16 + g;
            #pragma unroll
            for (int nt = 0; nt < 4; nt++) {
                const int lc = wn * 32 + nt * 8 + 2 * tk;
                const int blk = lc & ~31;
                const int k0 = lc & 31;
                const int p0 = ((k0 & 3) << 3) | (k0 >> 2);
                const int p1 = (((k0 + 1) & 3) << 3) | ((k0 + 1) >> 2);
                const float2 bv = *reinterpret_cast<const float2*>(bias + n0 + lc);
                es[lr * ERS + blk + p0]       = epi_op<true>(acc[mt][nt][0], bv.x);
                es[lr * ERS + blk + p1]       = epi_op<true>(acc[mt][nt][1], bv.y);
                es[(lr + 8) * ERS + blk + p0] = epi_op<true>(acc[mt][nt][2], bv.x);
                es[(lr + 8) * ERS + blk + p1] = epi_op<true>(acc[mt][nt][3], bv.y);
            }
        }
        __syncthreads();
        #pragma unroll
        for (int t = 0; t < 16; t++) {
            int idx = t * 256 + tid;          // 0..4095
            int row = idx >> 5;               // 0..127
            int c4  = idx & 31;               // float4 column
            float4 v = *reinterpret_cast<const float4*>(es + row * ERS + c4 * 4);
            *reinterpret_cast<float4*>(C + (size_t)(m0 + row) * NG + n0 + c4 * 4) = v;
        }
    } else {
        // GEMM2: bias only, direct float2 stores (already sector-efficient).
        #pragma unroll
        for (int mt = 0; mt < 4; mt++) {
            const int r = m0 + wm * 64 + mt * 16 + g;
            #pragma unroll
            for (int nt = 0; nt < 4; nt++) {
                const int cN = n0 + wn * 32 + nt * 8 + 2 * tk;
                const float2 bv = *reinterpret_cast<const float2*>(bias + cN);
                float2 v0, v1;
                v0.x = epi_op<false>(acc[mt][nt][0], bv.x);
                v0.y = epi_op<false>(acc[mt][nt][1], bv.y);
                v1.x = epi_op<false>(acc[mt][nt][2], bv.x);
                v1.y = epi_op<false>(acc[mt][nt][3], bv.y);
                *reinterpret_cast<float2*>(C + (size_t)(r)     * NG + cN) = v0;
                *reinterpret_cast<float2*>(C + (size_t)(r + 8) * NG + cN) = v1;
            }
        }
    }
}

// ---------------- launch ----------------
extern "C" void kernel_launch(void* const* d_in, const int* in_sizes, int n_in,
                              void* d_out, int out_size) {
    const float* x  = (const float*)d_in[0];   // [4,2048,1024] -> [8192,1024]
    const float* w1 = (const float*)d_in[1];   // [1024,4096]
    const float* b1 = (const float*)d_in[2];   // [4096]
    const float* w2 = (const float*)d_in[3];   // [4096,1024]
    const float* b2 = (const float*)d_in[4];   // [1024]
    float* out = (float*)d_out;                // [8192,1024]

    float *xr, *w1t, *w2t, *h;
    cudaGetSymbolAddress((void**)&xr,  g_xr);
    cudaGetSymbolAddress((void**)&w1t, g_w1t);
    cudaGetSymbolAddress((void**)&w2t, g_w2t);
    cudaGetSymbolAddress((void**)&h,   g_h);

    cudaFuncSetAttribute(mlp_gemm_kernel<1024, 4096, true>,
                         cudaFuncAttributeMaxDynamicSharedMemorySize, SMEM_TOTAL);
    cudaFuncSetAttribute(mlp_gemm_kernel<4096, 1024, false>,
                         cudaFuncAttributeMaxDynamicSharedMemorySize, SMEM_TOTAL);

    // prep: round to tf32 + k-permute X; transpose+round+permute weights to [N,K]
    {
        int n4 = 8192 * 1024 / 4;
        cvt_tf32_perm_kernel<<<(n4 + 255) / 256, 256>>>((const float4*)x, xr, 1024, n4);
        transpose_cvt_perm_kernel<<<dim3(4096 / 32, 1024 / 32), dim3(32, 8)>>>(w1, w1t, 1024, 4096);
        transpose_cvt_perm_kernel<<<dim3(1024 / 32, 4096 / 32), dim3(32, 8)>>>(w2, w2t, 4096, 1024);
    }

    // GEMM1: h = tf32(gelu(X @ W1 + b1))   [8192 x 4096], h stored k-permuted
    mlp_gemm_kernel<1024, 4096, true>
        <<<dim3(4096 / BN, 8192 / BM), THREADS, SMEM_TOTAL>>>(xr, w1t, b1, h);

    // GEMM2: out = h @ W2 + b2             [8192 x 1024]
    mlp_gemm_kernel<4096, 1024, false>
        <<<dim3(1024 / BN, 8192 / BM), THREADS, SMEM_TOTAL>>>(h, w2t, b2, out);
}